// round 9
// baseline (speedup 1.0000x reference)
#include <cuda_runtime.h>
#include <cuda_bf16.h>
#include <cstdint>

#define C_IN    64
#define K_OUT   64
#define H_IN    130
#define W_IN    130
#define H_OUT   128

// U in mma.sync B-fragment order: uint4 per (e, kslice, ks, lane) = {b0h,b1h,b0l,b1l}
__device__ uint4 g_Ufrag[36 * 8 * 4 * 32];   // 589 KB

__device__ const float d_ATx[24] = {
    1.f, 1.f,  1.f, 1.f,  1.f, 0.f,
    0.f, 1.f, -1.f, 2.f, -2.f, 0.f,
    0.f, 1.f,  1.f, 4.f,  4.f, 0.f,
    0.f, 1.f, -1.f, 8.f, -8.f, 1.f};

__device__ __forceinline__ uint32_t smem_u32(const void* p) {
    uint32_t a;
    asm("{ .reg .u64 t; cvta.to.shared.u64 t, %1; cvt.u32.u64 %0, t; }"
        : "=r"(a) : "l"(p));
    return a;
}

#define LDSM4(r, a)                                                          \
    asm volatile("ldmatrix.sync.aligned.m8n8.x4.shared.b16 {%0,%1,%2,%3}, [%4];" \
                 : "=r"((r)[0]), "=r"((r)[1]), "=r"((r)[2]), "=r"((r)[3])    \
                 : "r"(a))

#define MMA_BF16(c, a, b0, b1)                                               \
    asm volatile("mma.sync.aligned.m16n8k16.row.col.f32.bf16.bf16.f32 "      \
                 "{%0,%1,%2,%3},{%4,%5,%6,%7},{%8,%9},{%0,%1,%2,%3};"        \
                 : "+f"((c)[0]), "+f"((c)[1]), "+f"((c)[2]), "+f"((c)[3])    \
                 : "r"((a)[0]), "r"((a)[1]), "r"((a)[2]), "r"((a)[3]),       \
                   "r"(b0), "r"(b1))

// ---------------------------------------------------------------------------
// Kernel 1: filter transform -> g_Ufrag (fragment-order, hi/lo split)
// ---------------------------------------------------------------------------
__global__ void filter_transform(const float* __restrict__ w) {
    int c = threadIdx.x;
    int k = blockIdx.x;
    int a = blockIdx.y;

    constexpr float G[6][3] = {
        { 0.25f,     0.f,       0.f     },
        {-1.f/6.f,  -1.f/6.f,  -1.f/6.f },
        {-1.f/6.f,   1.f/6.f,  -1.f/6.f },
        { 1.f/24.f,  1.f/12.f,  1.f/6.f },
        { 1.f/24.f, -1.f/12.f,  1.f/6.f },
        { 0.f,       0.f,       1.f     }};

    const float* wp = w + (k * C_IN + c) * 9;
    float gw[3];
#pragma unroll
    for (int j = 0; j < 3; j++)
        gw[j] = G[a][0] * wp[0 * 3 + j] + G[a][1] * wp[1 * 3 + j] + G[a][2] * wp[2 * 3 + j];

    int wsl = k >> 3;
    int l   = (k & 7) * 4 + ((c & 7) >> 1);
    int ks  = c >> 4;
    int hh  = (c >> 3) & 1;
    int dd  = c & 1;
    unsigned short* ub = (unsigned short*)g_Ufrag;

#pragma unroll
    for (int b = 0; b < 6; b++) {
        float u = gw[0] * G[b][0] + gw[1] * G[b][1] + gw[2] * G[b][2];
        int e = a * 6 + b;
        size_t u4 = ((size_t)(e * 8 + wsl) * 4 + ks) * 32 + l;
        __nv_bfloat16 hi = __float2bfloat16_rn(u);
        __nv_bfloat16 lo = __float2bfloat16_rn(u - __bfloat162float(hi));
        ub[u4 * 8 + hh * 2 + dd]     = *(unsigned short*)&hi;
        ub[u4 * 8 + 4 + hh * 2 + dd] = *(unsigned short*)&lo;
    }
}

// ---------------------------------------------------------------------------
// Kernel 2: fully fused, 512 threads.
// 16 warps = 8 k-slices x 2 c-halves; warp = 16p x 8k x 32c.
// smem: V-all 36 x [hi 2K | lo 2K] = 144 KB (reused for Y reduction at end).
// ---------------------------------------------------------------------------
#define FUSED_SMEM 147456u

__global__ __launch_bounds__(512, 1) void winograd_fused(
        float* __restrict__ out, const float* __restrict__ x) {
    extern __shared__ __align__(128) char smem[];
    const uint32_t sb = smem_u32(smem);
    const int tid = threadIdx.x;
    const int lane = tid & 31;
    const int wid = tid >> 5;         // 0..15
    const int wk = wid >> 1;          // k-slice 0..7
    const int ch = wid & 1;           // c-half
    const int bx = blockIdx.x;        // 1024 = 16n x 32t x 2h
    const int n = bx >> 6;
    const int t = (bx >> 1) & 31;
    const int h = bx & 1;

    // B-fragment ring: 3 slots x 2 ks (this warp's c-half)
    uint4 Bf[3][2];
    const uint4* Ub = g_Ufrag;
#pragma unroll
    for (int kk = 0; kk < 2; kk++) {
        Bf[0][kk] = __ldg(&Ub[((0 * 8 + wk) * 4 + 2 * ch + kk) * 32 + lane]);
        Bf[1][kk] = __ldg(&Ub[((1 * 8 + wk) * 4 + 2 * ch + kk) * 32 + lane]);
    }

    // ---- phase 1: input transform, all 64 c in one shot ----
    constexpr float BT[6][6] = {
        {4.f, 0.f, -5.f,  0.f, 1.f, 0.f},
        {0.f,-4.f, -4.f,  1.f, 1.f, 0.f},
        {0.f, 4.f, -4.f, -1.f, 1.f, 0.f},
        {0.f,-2.f, -1.f,  2.f, 1.f, 0.f},
        {0.f, 2.f, -1.f, -2.f, 1.f, 0.f},
        {0.f, 4.f,  0.f, -5.f, 0.f, 1.f}};

    {
        int p_l = tid & 15;
        int c0  = (tid >> 4) * 2;     // 0..62
        const float* xb0 = x + ((size_t)(n * C_IN + c0) * H_IN + 4 * t) * W_IN
                             + (h * 16 + p_l) * 4;
        const float* xb1 = xb0 + (size_t)H_IN * W_IN;

        float t10[6][6], t11[6][6];
#pragma unroll
        for (int half = 0; half < 2; half++) {
            const float* xb = half ? xb1 : xb0;
            float d[6][6];
#pragma unroll
            for (int i = 0; i < 6; i++) {
                float2 v0 = *(const float2*)(xb + i * W_IN + 0);
                float2 v1 = *(const float2*)(xb + i * W_IN + 2);
                float2 v2 = *(const float2*)(xb + i * W_IN + 4);
                d[i][0] = v0.x; d[i][1] = v0.y;
                d[i][2] = v1.x; d[i][3] = v1.y;
                d[i][4] = v2.x; d[i][5] = v2.y;
            }
            float (*t1)[6] = half ? t11 : t10;
#pragma unroll
            for (int a = 0; a < 6; a++)
#pragma unroll
                for (int j = 0; j < 6; j++) {
                    float acc = 0.f;
#pragma unroll
                    for (int i = 0; i < 6; i++) acc += BT[a][i] * d[i][j];
                    t1[a][j] = acc;
                }
        }

        uint32_t swb = (uint32_t)(p_l * 128)
                     + ((uint32_t)((c0 >> 3) ^ (p_l & 7)) << 4) + (c0 & 7) * 2;
#pragma unroll
        for (int a = 0; a < 6; a++)
#pragma unroll
            for (int b = 0; b < 6; b++) {
                float v0 = 0.f, v1 = 0.f;
#pragma unroll
                for (int j = 0; j < 6; j++) {
                    v0 += t10[a][j] * BT[b][j];
                    v1 += t11[a][j] * BT[b][j];
                }
                float h0 = __bfloat162float(__float2bfloat16_rn(v0));
                float h1 = __bfloat162float(__float2bfloat16_rn(v1));
                uint32_t base = (uint32_t)(a * 6 + b) * 4096u + swb;
                *(__nv_bfloat162*)(smem + base) = __floats2bfloat162_rn(v0, v1);
                *(__nv_bfloat162*)(smem + base + 2048u) =
                    __floats2bfloat162_rn(v0 - h0, v1 - h1);
            }
    }
    __syncthreads();   // V complete; mainloop is barrier-free

    // ---- phase 2: 36-stage MMA (partial over this warp's c-half) ----
    float Y[4][4][4];
#pragma unroll
    for (int xx = 0; xx < 4; xx++)
#pragma unroll
        for (int q = 0; q < 4; q++)
#pragma unroll
            for (int y = 0; y < 4; y++) Y[xx][q][y] = 0.f;

    constexpr float ATC[4][6] = {
        {1.f, 1.f,  1.f, 1.f,  1.f, 0.f},
        {0.f, 1.f, -1.f, 2.f, -2.f, 0.f},
        {0.f, 1.f,  1.f, 4.f,  4.f, 0.f},
        {0.f, 1.f, -1.f, 8.f, -8.f, 1.f}};

    for (int a = 0; a < 6; a++) {
        float Z[4][4];
#pragma unroll
        for (int q = 0; q < 4; q++)
#pragma unroll
            for (int y = 0; y < 4; y++) Z[q][y] = 0.f;

#pragma unroll
        for (int b = 0; b < 6; b++) {
            const int e = a * 6 + b;
            if (e + 2 < 36) {
#pragma unroll
                for (int kk = 0; kk < 2; kk++)
                    Bf[(b + 2) % 3][kk] =
                        __ldg(&Ub[(((e + 2) * 8 + wk) * 4 + 2 * ch + kk) * 32 + lane]);
            }

            const uint32_t va = sb + (uint32_t)e * 4096u;
            float acc[4] = {0.f, 0.f, 0.f, 0.f};
#pragma unroll
            for (int kk = 0; kk < 2; kk++) {
                int ks = 2 * ch + kk;
                uint32_t Ah[4], Al[4];
                int rowA = lane & 15;
                int colA = (ks * 2 + (lane >> 4)) ^ (rowA & 7);
                uint32_t aA = va + (uint32_t)(rowA * 128 + colA * 16);
                LDSM4(Ah, aA);
                LDSM4(Al, aA + 2048u);
                const uint4 B = Bf[b % 3][kk];
                MMA_BF16(acc, Ah, B.x, B.y);   // hi*hi
                MMA_BF16(acc, Ah, B.z, B.w);   // hi*lo
                MMA_BF16(acc, Al, B.x, B.y);   // lo*hi
            }
#pragma unroll
            for (int q = 0; q < 4; q++)
#pragma unroll
                for (int y = 0; y < 4; y++)
                    Z[q][y] += ATC[y][b] * acc[q];
        }

        float cx0 = d_ATx[a], cx1 = d_ATx[6 + a], cx2 = d_ATx[12 + a], cx3 = d_ATx[18 + a];
#pragma unroll
        for (int q = 0; q < 4; q++)
#pragma unroll
            for (int y = 0; y < 4; y++) {
                float z = Z[q][y];
                Y[0][q][y] += cx0 * z;
                Y[1][q][y] += cx1 * z;
                Y[2][q][y] += cx2 * z;
                Y[3][q][y] += cx3 * z;
            }
    }

    // ---- cross-warp c-half reduction through smem (stride 65, conflict-free) ----
    __syncthreads();                  // all mainloop V reads done; smem reusable
    float* red = (float*)smem;
    const int r = wk * 32 + lane;     // 0..255, same for the warp pair
    if (ch == 1) {
#pragma unroll
        for (int xx = 0; xx < 4; xx++)
#pragma unroll
            for (int q = 0; q < 4; q++)
#pragma unroll
                for (int y = 0; y < 4; y++)
                    red[r * 65 + ((xx * 4 + q) * 4 + y)] = Y[xx][q][y];
    }
    __syncthreads();
    if (ch == 0) {
#pragma unroll
        for (int xx = 0; xx < 4; xx++)
#pragma unroll
            for (int q = 0; q < 4; q++)
#pragma unroll
                for (int y = 0; y < 4; y++)
                    Y[xx][q][y] += red[r * 65 + ((xx * 4 + q) * 4 + y)];

        // ---- epilogue: direct stores ----
        const int k0   = wk * 8 + (lane & 3) * 2;
        const int s_lo = lane >> 2;
#pragma unroll
        for (int q = 0; q < 4; q++) {
            int s = h * 16 + s_lo + ((q >> 1) << 3);
            int k = k0 + (q & 1);
            float* ob = out + ((size_t)(n * K_OUT + k) * H_OUT + t * 4) * H_OUT + s * 4;
#pragma unroll
            for (int xx = 0; xx < 4; xx++) {
                float4 v = make_float4(Y[xx][q][0], Y[xx][q][1], Y[xx][q][2], Y[xx][q][3]);
                *(float4*)&ob[(size_t)xx * H_OUT] = v;
            }
        }
    }
}

// ---------------------------------------------------------------------------
extern "C" void kernel_launch(void* const* d_in, const int* in_sizes, int n_in,
                              void* d_out, int out_size) {
    const float* x = (const float*)d_in[0];   // (16,64,130,130)
    const float* w = (const float*)d_in[1];   // (64,64,3,3)
    float* out = (float*)d_out;               // (16,64,128,128)

    cudaFuncSetAttribute(winograd_fused,
                         cudaFuncAttributeMaxDynamicSharedMemorySize, FUSED_SMEM);

    filter_transform<<<dim3(64, 6), 64>>>(w);
    winograd_fused<<<1024, 512, FUSED_SMEM>>>(out, x);
}

// round 10
// speedup vs baseline: 1.0315x; 1.0315x over previous
#include <cuda_runtime.h>
#include <cuda_bf16.h>
#include <cstdint>

#define C_IN    64
#define K_OUT   64
#define H_IN    130
#define W_IN    130
#define H_OUT   128

// U in mma.sync B-fragment order: uint4 per (e, kslice, ks, lane) = {b0h,b1h,b0l,b1l}
__device__ uint4 g_Ufrag[36 * 8 * 4 * 32];   // 589 KB

__device__ const float d_ATx[24] = {
    1.f, 1.f,  1.f, 1.f,  1.f, 0.f,
    0.f, 1.f, -1.f, 2.f, -2.f, 0.f,
    0.f, 1.f,  1.f, 4.f,  4.f, 0.f,
    0.f, 1.f, -1.f, 8.f, -8.f, 1.f};

__device__ __forceinline__ uint32_t smem_u32(const void* p) {
    uint32_t a;
    asm("{ .reg .u64 t; cvta.to.shared.u64 t, %1; cvt.u32.u64 %0, t; }"
        : "=r"(a) : "l"(p));
    return a;
}

#define LDSM4(r, a)                                                          \
    asm volatile("ldmatrix.sync.aligned.m8n8.x4.shared.b16 {%0,%1,%2,%3}, [%4];" \
                 : "=r"((r)[0]), "=r"((r)[1]), "=r"((r)[2]), "=r"((r)[3])    \
                 : "r"(a))

#define MMA_BF16(c, a, b0, b1)                                               \
    asm volatile("mma.sync.aligned.m16n8k16.row.col.f32.bf16.bf16.f32 "      \
                 "{%0,%1,%2,%3},{%4,%5,%6,%7},{%8,%9},{%0,%1,%2,%3};"        \
                 : "+f"((c)[0]), "+f"((c)[1]), "+f"((c)[2]), "+f"((c)[3])    \
                 : "r"((a)[0]), "r"((a)[1]), "r"((a)[2]), "r"((a)[3]),       \
                   "r"(b0), "r"(b1))

// ---------------------------------------------------------------------------
// Kernel 1: filter transform -> g_Ufrag (fragment-order, hi/lo split)
// ---------------------------------------------------------------------------
__global__ void filter_transform(const float* __restrict__ w) {
    int c = threadIdx.x;
    int k = blockIdx.x;
    int a = blockIdx.y;

    constexpr float G[6][3] = {
        { 0.25f,     0.f,       0.f     },
        {-1.f/6.f,  -1.f/6.f,  -1.f/6.f },
        {-1.f/6.f,   1.f/6.f,  -1.f/6.f },
        { 1.f/24.f,  1.f/12.f,  1.f/6.f },
        { 1.f/24.f, -1.f/12.f,  1.f/6.f },
        { 0.f,       0.f,       1.f     }};

    const float* wp = w + (k * C_IN + c) * 9;
    float gw[3];
#pragma unroll
    for (int j = 0; j < 3; j++)
        gw[j] = G[a][0] * wp[0 * 3 + j] + G[a][1] * wp[1 * 3 + j] + G[a][2] * wp[2 * 3 + j];

    int wsl = k >> 3;
    int l   = (k & 7) * 4 + ((c & 7) >> 1);
    int ks  = c >> 4;
    int hh  = (c >> 3) & 1;
    int dd  = c & 1;
    unsigned short* ub = (unsigned short*)g_Ufrag;

#pragma unroll
    for (int b = 0; b < 6; b++) {
        float u = gw[0] * G[b][0] + gw[1] * G[b][1] + gw[2] * G[b][2];
        int e = a * 6 + b;
        size_t u4 = ((size_t)(e * 8 + wsl) * 4 + ks) * 32 + l;
        __nv_bfloat16 hi = __float2bfloat16_rn(u);
        __nv_bfloat16 lo = __float2bfloat16_rn(u - __bfloat162float(hi));
        ub[u4 * 8 + hh * 2 + dd]     = *(unsigned short*)&hi;
        ub[u4 * 8 + 4 + hh * 2 + dd] = *(unsigned short*)&lo;
    }
}

// ---------------------------------------------------------------------------
// Kernel 2: fully fused — input transform + GEMM + output transform.
// CTA = half tile-row: 16 tiles (p) x 64 k, all 36 e. 256 threads, 8 warps.
// smem: V-all only, 36 x [hi 2K | lo 2K] = 144 KB.
// U straight from gmem (L2-hot) into registers, prefetch depth 2.
// Accumulator split into 3 independent chains (hh/hl/lh) for MMA ILP.
// ---------------------------------------------------------------------------
#define FUSED_SMEM 147456u

__global__ __launch_bounds__(256, 1) void winograd_fused(
        float* __restrict__ out, const float* __restrict__ x) {
    extern __shared__ __align__(128) char smem[];
    const uint32_t sb = smem_u32(smem);
    const int tid = threadIdx.x;
    const int lane = tid & 31;
    const int wn = tid >> 5;          // warp -> 8k slice
    const int bx = blockIdx.x;        // 1024 = 16n x 32t x 2h
    const int n = bx >> 6;
    const int t = (bx >> 1) & 31;
    const int h = bx & 1;

    // B-fragment ring (3 bufs; e % 3 == b % 3 since 6 % 3 == 0)
    uint4 Bf[3][4];
    const uint4* Ub = g_Ufrag;
#pragma unroll
    for (int ks = 0; ks < 4; ks++)
        Bf[0][ks] = __ldg(&Ub[((0 * 8 + wn) * 4 + ks) * 32 + lane]);
#pragma unroll
    for (int ks = 0; ks < 4; ks++)
        Bf[1][ks] = __ldg(&Ub[((1 * 8 + wn) * 4 + ks) * 32 + lane]);

    // ---- phase 1: input transform, c-pairs, bf16x2 packed stores ----
    constexpr float BT[6][6] = {
        {4.f, 0.f, -5.f,  0.f, 1.f, 0.f},
        {0.f,-4.f, -4.f,  1.f, 1.f, 0.f},
        {0.f, 4.f, -4.f, -1.f, 1.f, 0.f},
        {0.f,-2.f, -1.f,  2.f, 1.f, 0.f},
        {0.f, 2.f, -1.f, -2.f, 1.f, 0.f},
        {0.f, 4.f,  0.f, -5.f, 0.f, 1.f}};

#pragma unroll
    for (int iter = 0; iter < 2; iter++) {
        int p_l = tid & 15;
        int c0  = iter * 32 + (tid >> 4) * 2;
        const float* xb0 = x + ((size_t)(n * C_IN + c0) * H_IN + 4 * t) * W_IN
                             + (h * 16 + p_l) * 4;
        const float* xb1 = xb0 + (size_t)H_IN * W_IN;

        float t10[6][6], t11[6][6];
#pragma unroll
        for (int half = 0; half < 2; half++) {
            const float* xb = half ? xb1 : xb0;
            float d[6][6];
#pragma unroll
            for (int i = 0; i < 6; i++) {
                float2 v0 = *(const float2*)(xb + i * W_IN + 0);
                float2 v1 = *(const float2*)(xb + i * W_IN + 2);
                float2 v2 = *(const float2*)(xb + i * W_IN + 4);
                d[i][0] = v0.x; d[i][1] = v0.y;
                d[i][2] = v1.x; d[i][3] = v1.y;
                d[i][4] = v2.x; d[i][5] = v2.y;
            }
            float (*t1)[6] = half ? t11 : t10;
#pragma unroll
            for (int a = 0; a < 6; a++)
#pragma unroll
                for (int j = 0; j < 6; j++) {
                    float acc = 0.f;
#pragma unroll
                    for (int i = 0; i < 6; i++) acc += BT[a][i] * d[i][j];
                    t1[a][j] = acc;
                }
        }

        uint32_t swb = (uint32_t)(p_l * 128)
                     + ((uint32_t)((c0 >> 3) ^ (p_l & 7)) << 4) + (c0 & 7) * 2;
#pragma unroll
        for (int a = 0; a < 6; a++)
#pragma unroll
            for (int b = 0; b < 6; b++) {
                float v0 = 0.f, v1 = 0.f;
#pragma unroll
                for (int j = 0; j < 6; j++) {
                    v0 += t10[a][j] * BT[b][j];
                    v1 += t11[a][j] * BT[b][j];
                }
                float h0 = __bfloat162float(__float2bfloat16_rn(v0));
                float h1 = __bfloat162float(__float2bfloat16_rn(v1));
                uint32_t base = (uint32_t)(a * 6 + b) * 4096u + swb;
                *(__nv_bfloat162*)(smem + base) = __floats2bfloat162_rn(v0, v1);
                *(__nv_bfloat162*)(smem + base + 2048u) =
                    __floats2bfloat162_rn(v0 - h0, v1 - h1);
            }
    }
    __syncthreads();   // V complete; mainloop is barrier-free

    // ---- phase 2: 36-stage MMA + fused output transform ----
    float Y[4][4][4];
#pragma unroll
    for (int xx = 0; xx < 4; xx++)
#pragma unroll
        for (int q = 0; q < 4; q++)
#pragma unroll
            for (int y = 0; y < 4; y++) Y[xx][q][y] = 0.f;

    constexpr float ATC[4][6] = {
        {1.f, 1.f,  1.f, 1.f,  1.f, 0.f},
        {0.f, 1.f, -1.f, 2.f, -2.f, 0.f},
        {0.f, 1.f,  1.f, 4.f,  4.f, 0.f},
        {0.f, 1.f, -1.f, 8.f, -8.f, 1.f}};

    for (int a = 0; a < 6; a++) {
        float Z[4][4];
#pragma unroll
        for (int q = 0; q < 4; q++)
#pragma unroll
            for (int y = 0; y < 4; y++) Z[q][y] = 0.f;

#pragma unroll
        for (int b = 0; b < 6; b++) {
            const int e = a * 6 + b;
            if (e + 2 < 36) {
#pragma unroll
                for (int ks = 0; ks < 4; ks++)
                    Bf[(b + 2) % 3][ks] =
                        __ldg(&Ub[(((e + 2) * 8 + wn) * 4 + ks) * 32 + lane]);
            }

            const uint32_t va = sb + (uint32_t)e * 4096u;
            // 3 independent accumulator chains: hh / hl / lh
            float accT[3][4];
#pragma unroll
            for (int tt = 0; tt < 3; tt++)
#pragma unroll
                for (int q = 0; q < 4; q++) accT[tt][q] = 0.f;

#pragma unroll
            for (int ks = 0; ks < 4; ks++) {
                uint32_t Ah[4], Al[4];
                int rowA = lane & 15;
                int colA = (ks * 2 + (lane >> 4)) ^ (rowA & 7);
                uint32_t aA = va + (uint32_t)(rowA * 128 + colA * 16);
                LDSM4(Ah, aA);
                LDSM4(Al, aA + 2048u);
                const uint4 B = Bf[b % 3][ks];
                MMA_BF16(accT[0], Ah, B.x, B.y);   // hi*hi
                MMA_BF16(accT[1], Ah, B.z, B.w);   // hi*lo
                MMA_BF16(accT[2], Al, B.x, B.y);   // lo*hi
            }
#pragma unroll
            for (int q = 0; q < 4; q++) {
                float m0 = (accT[0][q] + accT[1][q]) + accT[2][q];
#pragma unroll
                for (int y = 0; y < 4; y++)
                    Z[q][y] += ATC[y][b] * m0;
            }
        }

        float cx0 = d_ATx[a], cx1 = d_ATx[6 + a], cx2 = d_ATx[12 + a], cx3 = d_ATx[18 + a];
#pragma unroll
        for (int q = 0; q < 4; q++)
#pragma unroll
            for (int y = 0; y < 4; y++) {
                float z = Z[q][y];
                Y[0][q][y] += cx0 * z;
                Y[1][q][y] += cx1 * z;
                Y[2][q][y] += cx2 * z;
                Y[3][q][y] += cx3 * z;
            }
    }

    // ---- epilogue: direct stores ----
    const int k0   = wn * 8 + (lane & 3) * 2;
    const int s_lo = lane >> 2;
#pragma unroll
    for (int q = 0; q < 4; q++) {
        int s = h * 16 + s_lo + ((q >> 1) << 3);
        int k = k0 + (q & 1);
        float* ob = out + ((size_t)(n * K_OUT + k) * H_OUT + t * 4) * H_OUT + s * 4;
#pragma unroll
        for (int xx = 0; xx < 4; xx++) {
            float4 v = make_float4(Y[xx][q][0], Y[xx][q][1], Y[xx][q][2], Y[xx][q][3]);
            *(float4*)&ob[(size_t)xx * H_OUT] = v;
        }
    }
}

// ---------------------------------------------------------------------------
extern "C" void kernel_launch(void* const* d_in, const int* in_sizes, int n_in,
                              void* d_out, int out_size) {
    const float* x = (const float*)d_in[0];   // (16,64,130,130)
    const float* w = (const float*)d_in[1];   // (64,64,3,3)
    float* out = (float*)d_out;               // (16,64,128,128)

    cudaFuncSetAttribute(winograd_fused,
                         cudaFuncAttributeMaxDynamicSharedMemorySize, FUSED_SMEM);

    filter_transform<<<dim3(64, 6), 64>>>(w);
    winograd_fused<<<1024, 256, FUSED_SMEM>>>(out, x);
}